// round 15
// baseline (speedup 1.0000x reference)
#include <cuda_runtime.h>
#include <cuda_fp16.h>
#include <cstdint>

#define DIMSZ 768
#define NTOK 1024
#define BATCH 8
#define HEADS 12
#define DH 64
#define NROWS (BATCH * NTOK)      /* 8192 */
#define QKVN (3 * DIMSZ)          /* 2304 */
#define SCALE 0.125f              /* DH^-0.5 */

typedef unsigned short u16;
typedef uint32_t u32;

// ---------------- scratch (device globals, allocation-free) ----------------
__device__ u16 g_xnh[NROWS * DIMSZ];     // LN out, fp16
__device__ u16 g_wqh[QKVN * DIMSZ];      // Wqkv^T fp16
__device__ u16 g_woh[DIMSZ * DIMSZ];     // Wout^T fp16
__device__ u16 g_qkvh[NROWS * QKVN];     // qkv fp16
__device__ u16 g_vth[BATCH * HEADS * DH * NTOK];   // V^T fp16
__device__ u16 g_atth[NROWS * DIMSZ];    // attention out fp16

// ---------------- helpers ----------------
__device__ __forceinline__ u32 smem_u32(const void* p) {
    u32 a;
    asm("{ .reg .u64 t; cvta.to.shared.u64 t, %1; cvt.u32.u64 %0, t; }" : "=r"(a) : "l"(p));
    return a;
}
__device__ __forceinline__ void ldsm_x4(u32 addr, u32* r) {
    asm volatile("ldmatrix.sync.aligned.m8n8.x4.shared.b16 {%0,%1,%2,%3}, [%4];"
                 : "=r"(r[0]), "=r"(r[1]), "=r"(r[2]), "=r"(r[3]) : "r"(addr));
}
__device__ __forceinline__ void mma16816(float* c, const u32* a, u32 b0, u32 b1) {
    asm volatile("mma.sync.aligned.m16n8k16.row.col.f32.f16.f16.f32 "
                 "{%0,%1,%2,%3}, {%4,%5,%6,%7}, {%8,%9}, {%0,%1,%2,%3};"
                 : "+f"(c[0]), "+f"(c[1]), "+f"(c[2]), "+f"(c[3])
                 : "r"(a[0]), "r"(a[1]), "r"(a[2]), "r"(a[3]), "r"(b0), "r"(b1));
}
#define CP16(dst, src) \
    asm volatile("cp.async.cg.shared.global [%0], [%1], 16;" :: "r"(dst), "l"(src))
#define CP_COMMIT() asm volatile("cp.async.commit_group;" ::: "memory")
#define CP_WAIT0()  asm volatile("cp.async.wait_group 0;" ::: "memory")
#define CP_WAIT1()  asm volatile("cp.async.wait_group 1;" ::: "memory")

__device__ __forceinline__ u32 pack2h(float a, float b) {
    __half2 v = __floats2half2_rn(a, b);
    return *(u32*)&v;
}
__device__ __forceinline__ u16 h16(float a) {
    return __half_as_ushort(__float2half_rn(a));
}

// ===========================================================================
// LayerNorm -> fp16
// ===========================================================================
__global__ __launch_bounds__(256) void ln_kernel(const float* __restrict__ x,
                                                 const float* __restrict__ gamma,
                                                 const float* __restrict__ beta,
                                                 u16* __restrict__ yh) {
    int row = blockIdx.x;
    int t = threadIdx.x;
    __shared__ float sv[DIMSZ];
    __shared__ float sb[8], ssb[8];
    __shared__ float smu, srstd;
    const float* xr = x + (size_t)row * DIMSZ;
    float v0 = xr[t], v1 = xr[t + 256], v2 = xr[t + 512];
    float s = v0 + v1 + v2;
    float ss = v0 * v0 + v1 * v1 + v2 * v2;
#pragma unroll
    for (int o = 16; o > 0; o >>= 1) {
        s += __shfl_xor_sync(0xffffffffu, s, o);
        ss += __shfl_xor_sync(0xffffffffu, ss, o);
    }
    if ((t & 31) == 0) { sb[t >> 5] = s; ssb[t >> 5] = ss; }
    __syncthreads();
    if (t == 0) {
        float S = 0.f, SS = 0.f;
#pragma unroll
        for (int i = 0; i < 8; i++) { S += sb[i]; SS += ssb[i]; }
        float mu = S * (1.0f / DIMSZ);
        float var = SS * (1.0f / DIMSZ) - mu * mu;
        smu = mu;
        srstd = rsqrtf(var + 1e-5f);
    }
    __syncthreads();
    float mu = smu, rstd = srstd;
    sv[t]       = (v0 - mu) * rstd * gamma[t]       + beta[t];
    sv[t + 256] = (v1 - mu) * rstd * gamma[t + 256] + beta[t + 256];
    sv[t + 512] = (v2 - mu) * rstd * gamma[t + 512] + beta[t + 512];
    __syncthreads();
    u32* oh = (u32*)(yh + (size_t)row * DIMSZ);
    for (int p = t; p < DIMSZ / 2; p += 256)
        oh[p] = pack2h(sv[2 * p], sv[2 * p + 1]);
}

// ===========================================================================
// Weight transpose to fp16 (both weights in one launch, z selects)
// ===========================================================================
__global__ __launch_bounds__(256) void wprep_kernel(const float* __restrict__ Wq,
                                                    const float* __restrict__ Wo,
                                                    u16* __restrict__ Wqt,
                                                    u16* __restrict__ Wot) {
    const float* W;
    u16* Wt;
    int Nsz;
    if (blockIdx.z == 0) { W = Wq; Wt = Wqt; Nsz = QKVN; }
    else {
        if (blockIdx.x >= DIMSZ / 32) return;
        W = Wo; Wt = Wot; Nsz = DIMSZ;
    }
    __shared__ float sm[32][33];
    int tx = threadIdx.x & 31, ty = threadIdx.x >> 5;   // 32 x 8
    int n0 = blockIdx.x * 32, k0 = blockIdx.y * 32;
#pragma unroll
    for (int i = 0; i < 4; i++)
        sm[ty + i * 8][tx] = W[(size_t)(k0 + ty + i * 8) * Nsz + n0 + tx];
    __syncthreads();
#pragma unroll
    for (int i = 0; i < 4; i++) {
        int n = n0 + ty + i * 8, k = k0 + tx;
        Wt[(size_t)n * DIMSZ + k] = h16(sm[tx][ty + i * 8]);
    }
}

// ===========================================================================
// V transpose: qkv V part [b][j][h*64+d] -> vt [b][h][d][j]
// ===========================================================================
__global__ __launch_bounds__(256) void vtrans_kernel(const u16* __restrict__ qh,
                                                     u16* __restrict__ vh) {
    __shared__ u16 sm[64][66];
    int t = threadIdx.x;
    int j0 = blockIdx.x * 64, h = blockIdx.y, b = blockIdx.z;
#pragma unroll
    for (int i = 0; i < 8; i++) {
        int id = t + i * 256;          // 0..2047
        int jj = id >> 5, dp = id & 31;
        u32 v = *(const u32*)(qh + (size_t)(b * NTOK + j0 + jj) * QKVN +
                              2 * DIMSZ + h * DH + dp * 2);
        sm[jj][2 * dp] = (u16)v;
        sm[jj][2 * dp + 1] = (u16)(v >> 16);
    }
    __syncthreads();
#pragma unroll
    for (int i = 0; i < 8; i++) {
        int id = t + i * 256;
        int d = id >> 5, jp = id & 31;
        u32 v = (u32)sm[2 * jp][d] | ((u32)sm[2 * jp + 1][d] << 16);
        *(u32*)(vh + ((size_t)((b * HEADS + h) * DH + d)) * NTOK + j0 + 2 * jp) = v;
    }
}

// ===========================================================================
// fp16 1-term GEMM: C[M,N] = A[M,768] @ B[N,768]^T (+bias)
// CTA 128x128, 512 thr (16 warps, 32x32 tiles), KC=64, NBUF=3 cp.async.
// EPI 0: fp32 out + bias.  EPI 1: fp16 out, SCALE folded on n<768.
// ===========================================================================
#define TROW 144                  /* 64 fp16 (128B) + 16B pad */
#define TILE (128 * TROW)         /* 18432 */
#define STAGE (2 * TILE)          /* 36864: A, B */
#define NBUF 3
#define GEMM_SMEM (NBUF * STAGE)  /* 110592 */
#define KC 64
#define NSTAGE (DIMSZ / KC)       /* 12 */
#define B_OFF TILE

template <int EPI>
__global__ __launch_bounds__(512, 1) void mma_gemm(const u16* __restrict__ Ah,
                                                   const u16* __restrict__ Bh,
                                                   const float* __restrict__ bias,
                                                   float* __restrict__ Cf,
                                                   u16* __restrict__ Ch,
                                                   int Nsz) {
    extern __shared__ char smem[];
    const u32 smb = smem_u32(smem);
    const int t = threadIdx.x;
    const int wid = t >> 5, lane = t & 31;
    const int m0 = blockIdx.y * 128, n0 = blockIdx.x * 128;
    const int wm = (wid >> 2) * 32, wn = (wid & 3) * 32;

    float acc[2][4][4];
#pragma unroll
    for (int i = 0; i < 2; i++)
#pragma unroll
        for (int j = 0; j < 4; j++)
#pragma unroll
            for (int k = 0; k < 4; k++) acc[i][j][k] = 0.f;

    const int frow = t >> 2;          // 0..127
    const int q4 = t & 3;             // 16-elem quarter

    auto fill = [&](int c) {
        const u32 base = smb + (c % NBUF) * STAGE;
        const size_t aoff = (size_t)(m0 + frow) * DIMSZ + c * KC + q4 * 16;
        const size_t boff = (size_t)(n0 + frow) * DIMSZ + c * KC + q4 * 16;
        const u32 doff = (u32)(frow * TROW + q4 * 32);
        CP16(base + doff, Ah + aoff);
        CP16(base + doff + 16, Ah + aoff + 8);
        CP16(base + B_OFF + doff, Bh + boff);
        CP16(base + B_OFF + doff + 16, Bh + boff + 8);
    };

    const int brow = ((lane >> 4) << 3) + (lane & 7);

    auto compute = [&](int c) {
        const u32 base = smb + (c % NBUF) * STAGE;
#pragma unroll
        for (int ks = 0; ks < 4; ks++) {
            u32 Ahf[2][4], Bhf[2][4];
            const u32 akb = (u32)(ks * 32 + ((lane & 16) ? 16 : 0));
#pragma unroll
            for (int mt = 0; mt < 2; mt++) {
                u32 ra = base + (u32)((wm + mt * 16 + (lane & 15)) * TROW) + akb;
                ldsm_x4(ra, Ahf[mt]);
            }
            const u32 bkb = (u32)(ks * 32 + ((lane & 8) ? 16 : 0));
#pragma unroll
            for (int bt = 0; bt < 2; bt++) {
                u32 rb = base + B_OFF + (u32)((wn + bt * 16 + brow) * TROW) + bkb;
                ldsm_x4(rb, Bhf[bt]);
            }
#pragma unroll
            for (int mt = 0; mt < 2; mt++)
#pragma unroll
                for (int nt = 0; nt < 4; nt++)
                    mma16816(acc[mt][nt], Ahf[mt],
                             Bhf[nt >> 1][(nt & 1) * 2], Bhf[nt >> 1][(nt & 1) * 2 + 1]);
        }
    };

    fill(0); CP_COMMIT();
    fill(1); CP_COMMIT();
    for (int c = 0; c < NSTAGE; c++) {
        CP_WAIT1();
        __syncthreads();
        if (c + 2 < NSTAGE) fill(c + 2);
        CP_COMMIT();
        compute(c);
    }

    // epilogue
#pragma unroll
    for (int mt = 0; mt < 2; mt++) {
        int m = m0 + wm + mt * 16 + (lane >> 2);
#pragma unroll
        for (int nt = 0; nt < 4; nt++) {
            int n = n0 + wn + nt * 8 + (lane & 3) * 2;
            if (EPI == 0) {
                float bx = bias[n], by = bias[n + 1];
                *(float2*)&Cf[(size_t)m * Nsz + n] =
                    make_float2(acc[mt][nt][0] + bx, acc[mt][nt][1] + by);
                *(float2*)&Cf[(size_t)(m + 8) * Nsz + n] =
                    make_float2(acc[mt][nt][2] + bx, acc[mt][nt][3] + by);
            } else {
                float sc = (n < DIMSZ) ? SCALE : 1.0f;
                *(u32*)(Ch + (size_t)m * Nsz + n) =
                    pack2h(acc[mt][nt][0] * sc, acc[mt][nt][1] * sc);
                *(u32*)(Ch + (size_t)(m + 8) * Nsz + n) =
                    pack2h(acc[mt][nt][2] * sc, acc[mt][nt][3] * sc);
            }
        }
    }
}

// ===========================================================================
// Attention, 1-term fp16. 128 keys per cp.async stage (two 64-key sub-tiles
// per barrier window -> half the barriers, wider warp-drift window).
// Block = 256 thr (8 warps), one (b,h,128-q-row tile).
// ===========================================================================
#define AROW 144
#define QTILE (128 * AROW)           /* 18432 */
#define KTILE (64 * AROW)            /* 9216 */
#define AKVB (4 * KTILE)             /* K0,V0,K1,V1 = 36864 */
#define ASMEM (QTILE + 2 * AKVB)     /* 92160; x2 CTAs = 184320 */

__global__ __launch_bounds__(256, 2) void attn_mma(const u16* __restrict__ qh,
                                                   const u16* __restrict__ vth,
                                                   const float* __restrict__ rpb,
                                                   u16* __restrict__ oh) {
    extern __shared__ char smem[];
    const u32 smb = smem_u32(smem);
    const int t = threadIdx.x;
    const int w = t >> 5, lane = t & 31;
    const int i0 = blockIdx.x * 128, h = blockIdx.y, b = blockIdx.z;

    const int brow = ((lane >> 4) << 3) + (lane & 7);

    // ---- Q tile (128 rows) -> smem ----
    {
        const int frow = t >> 1, half = t & 1;
        const size_t qoff = (size_t)(b * NTOK + i0 + frow) * QKVN + h * DH + half * 32;
        const u32 doff = (u32)(frow * AROW + half * 64);
#pragma unroll
        for (int i = 0; i < 4; i++)
            CP16(smb + doff + i * 16, qh + qoff + i * 8);
        CP_COMMIT();
    }

    // load 128 keys (two 64-key K and V sub-tiles) per stage
    auto fillKV = [&](int jt) {
        const u32 base = smb + QTILE + (jt & 1) * AKVB;
        const int row = t >> 2, q4 = t & 3;
        const u32 doff = (u32)(row * AROW + q4 * 32);
#pragma unroll
        for (int sσ = 0; sσ < 2; sσ++) {
            const size_t koff = (size_t)(b * NTOK + jt * 128 + sσ * 64 + row) * QKVN + DIMSZ + h * DH + q4 * 16;
            const size_t voff = (size_t)((b * HEADS + h) * DH + row) * NTOK + jt * 128 + sσ * 64 + q4 * 16;
            const u32 sb2 = base + sσ * 2 * KTILE;
            CP16(sb2 + doff, qh + koff);
            CP16(sb2 + doff + 16, qh + koff + 8);
            CP16(sb2 + KTILE + doff, vth + voff);
            CP16(sb2 + KTILE + doff + 16, vth + voff + 8);
        }
    };

    fillKV(0); CP_COMMIT();

    CP_WAIT1();
    __syncthreads();
    u32 Aqh[4][4];
#pragma unroll
    for (int ks = 0; ks < 4; ks++) {
        u32 ra = smb + (u32)((w * 16 + (lane & 15)) * AROW) + ks * 32 + ((lane & 16) ? 16 : 0);
        ldsm_x4(ra, Aqh[ks]);
    }

    float o[8][4];
#pragma unroll
    for (int nt = 0; nt < 8; nt++)
#pragma unroll
        for (int k = 0; k < 4; k++) o[nt][k] = 0.f;
    float mA = -1e30f, mB = -1e30f, lA = 0.f, lB = 0.f;

    const float* bp = rpb + ((size_t)(h * NTOK + i0 + w * 16 + (lane >> 2))) * NTOK + 2 * (lane & 3);

    for (int jt = 0; jt < 8; jt++) {
        CP_WAIT0();
        __syncthreads();
        if (jt + 1 < 8) { fillKV(jt + 1); CP_COMMIT(); }

#pragma unroll
        for (int sub = 0; sub < 2; sub++) {
            const u32 kb = smb + QTILE + (jt & 1) * AKVB + sub * 2 * KTILE;
            const u32 vb = kb + KTILE;

            // ---- S = Q K^T ----
            float s[8][4];
#pragma unroll
            for (int nt = 0; nt < 8; nt++)
#pragma unroll
                for (int k = 0; k < 4; k++) s[nt][k] = 0.f;
#pragma unroll
            for (int ks = 0; ks < 4; ks++) {
                u32 Bf[4][4];
                const u32 bkb = (u32)(ks * 32 + ((lane & 8) ? 16 : 0));
#pragma unroll
                for (int bt = 0; bt < 4; bt++) {
                    u32 rb = kb + (u32)((bt * 16 + brow) * AROW) + bkb;
                    ldsm_x4(rb, Bf[bt]);
                }
#pragma unroll
                for (int nt = 0; nt < 8; nt++)
                    mma16816(s[nt], Aqh[ks],
                             Bf[nt >> 1][(nt & 1) * 2], Bf[nt >> 1][(nt & 1) * 2 + 1]);
            }

            // ---- + bias, online softmax ----
            const float* bpj = bp + jt * 128 + sub * 64;
            float tmA = -1e30f, tmB = -1e30f;
#pragma unroll
            for (int nt = 0; nt < 8; nt++) {
                float2 ba = *(const float2*)(bpj + nt * 8);
                float2 bb = *(const float2*)(bpj + 8 * NTOK + nt * 8);
                s[nt][0] += ba.x; s[nt][1] += ba.y;
                s[nt][2] += bb.x; s[nt][3] += bb.y;
                tmA = fmaxf(tmA, fmaxf(s[nt][0], s[nt][1]));
                tmB = fmaxf(tmB, fmaxf(s[nt][2], s[nt][3]));
            }
            tmA = fmaxf(tmA, __shfl_xor_sync(0xffffffffu, tmA, 1));
            tmA = fmaxf(tmA, __shfl_xor_sync(0xffffffffu, tmA, 2));
            tmB = fmaxf(tmB, __shfl_xor_sync(0xffffffffu, tmB, 1));
            tmB = fmaxf(tmB, __shfl_xor_sync(0xffffffffu, tmB, 2));
            float nmA = fmaxf(mA, tmA), nmB = fmaxf(mB, tmB);
            float facA = __expf(mA - nmA), facB = __expf(mB - nmB);
            mA = nmA; mB = nmB;
            float suA = 0.f, suB = 0.f;
#pragma unroll
            for (int nt = 0; nt < 8; nt++) {
                s[nt][0] = __expf(s[nt][0] - mA);
                s[nt][1] = __expf(s[nt][1] - mA);
                s[nt][2] = __expf(s[nt][2] - mB);
                s[nt][3] = __expf(s[nt][3] - mB);
                suA += s[nt][0] + s[nt][1];
                suB += s[nt][2] + s[nt][3];
                o[nt][0] *= facA; o[nt][1] *= facA;
                o[nt][2] *= facB; o[nt][3] *= facB;
            }
            suA += __shfl_xor_sync(0xffffffffu, suA, 1);
            suA += __shfl_xor_sync(0xffffffffu, suA, 2);
            suB += __shfl_xor_sync(0xffffffffu, suB, 1);
            suB += __shfl_xor_sync(0xffffffffu, suB, 2);
            lA = lA * facA + suA;
            lB = lB * facB + suB;

            // ---- P fragments (fp16) ----
            u32 Aph[4][4];
#pragma unroll
            for (int kt = 0; kt < 4; kt++) {
                Aph[kt][0] = pack2h(s[2 * kt][0], s[2 * kt][1]);
                Aph[kt][1] = pack2h(s[2 * kt][2], s[2 * kt][3]);
                Aph[kt][2] = pack2h(s[2 * kt + 1][0], s[2 * kt + 1][1]);
                Aph[kt][3] = pack2h(s[2 * kt + 1][2], s[2 * kt + 1][3]);
            }

            // ---- O += P V, V^T in smem [d][j] ----
#pragma unroll
            for (int kt = 0; kt < 4; kt++) {
                u32 Bf[4][4];
                const u32 bkb = (u32)(kt * 32 + ((lane & 8) ? 16 : 0));
#pragma unroll
                for (int bt = 0; bt < 4; bt++) {
                    u32 rb = vb + (u32)((bt * 16 + brow) * AROW) + bkb;
                    ldsm_x4(rb, Bf[bt]);
                }
#pragma unroll
                for (int nt = 0; nt < 8; nt++)
                    mma16816(o[nt], Aph[kt],
                             Bf[nt >> 1][(nt & 1) * 2], Bf[nt >> 1][(nt & 1) * 2 + 1]);
            }
        }
    }

    // ---- epilogue: normalize, store fp16 ----
    float invA = 1.0f / lA, invB = 1.0f / lB;
    int rowA = b * NTOK + i0 + w * 16 + (lane >> 2);
#pragma unroll
    for (int nt = 0; nt < 8; nt++) {
        int col = h * DH + nt * 8 + 2 * (lane & 3);
        *(u32*)(oh + (size_t)rowA * DIMSZ + col) = pack2h(o[nt][0] * invA, o[nt][1] * invA);
        *(u32*)(oh + (size_t)(rowA + 8) * DIMSZ + col) = pack2h(o[nt][2] * invB, o[nt][3] * invB);
    }
}

// ---------------------------------------------------------------------------
extern "C" void kernel_launch(void* const* d_in, const int* in_sizes, int n_in,
                              void* d_out, int out_size) {
    const float* x    = (const float*)d_in[0];
    const float* rpb  = (const float*)d_in[1];
    const float* Wqkv = (const float*)d_in[2];
    const float* Wout = (const float*)d_in[3];
    const float* bout = (const float*)d_in[4];
    const float* lng  = (const float*)d_in[5];
    const float* lnb  = (const float*)d_in[6];
    float* out = (float*)d_out;

    u16 *xnh, *wqh, *woh, *qkh, *vth, *ath;
    cudaGetSymbolAddress((void**)&xnh, g_xnh);
    cudaGetSymbolAddress((void**)&wqh, g_wqh);
    cudaGetSymbolAddress((void**)&woh, g_woh);
    cudaGetSymbolAddress((void**)&qkh, g_qkvh);
    cudaGetSymbolAddress((void**)&vth, g_vth);
    cudaGetSymbolAddress((void**)&ath, g_atth);

    // 1) LN -> fp16
    ln_kernel<<<NROWS, 256>>>(x, lng, lnb, xnh);

    // 1b) weight prep (both weights, one launch)
    wprep_kernel<<<dim3(QKVN / 32, DIMSZ / 32, 2), 256>>>(Wqkv, Wout, wqh, woh);

    // 2) QKV projection (1-term, fp16 out, Q pre-scaled)
    cudaFuncSetAttribute(mma_gemm<1>, cudaFuncAttributeMaxDynamicSharedMemorySize, GEMM_SMEM);
    mma_gemm<1><<<dim3(QKVN / 128, NROWS / 128), 512, GEMM_SMEM>>>(
        xnh, wqh, nullptr, nullptr, qkh, QKVN);

    // 2b) V transpose
    vtrans_kernel<<<dim3(NTOK / 64, HEADS, BATCH), 256>>>(qkh, vth);

    // 3) attention (1-term fp16, 128-key stages)
    cudaFuncSetAttribute(attn_mma, cudaFuncAttributeMaxDynamicSharedMemorySize, ASMEM);
    attn_mma<<<dim3(NTOK / 128, HEADS, BATCH), 256, ASMEM>>>(
        qkh, vth, rpb, ath);

    // 4) output projection (1-term, fp32 out + bias)
    cudaFuncSetAttribute(mma_gemm<0>, cudaFuncAttributeMaxDynamicSharedMemorySize, GEMM_SMEM);
    mma_gemm<0><<<dim3(DIMSZ / 128, NROWS / 128), 512, GEMM_SMEM>>>(
        ath, woh, bout, out, nullptr, DIMSZ);
}

// round 16
// speedup vs baseline: 1.5739x; 1.5739x over previous
#include <cuda_runtime.h>
#include <cuda_fp16.h>
#include <cstdint>

#define DIMSZ 768
#define NTOK 1024
#define BATCH 8
#define HEADS 12
#define DH 64
#define NROWS (BATCH * NTOK)      /* 8192 */
#define QKVN (3 * DIMSZ)          /* 2304 */
#define SCALE 0.125f              /* DH^-0.5 */

typedef unsigned short u16;
typedef uint32_t u32;

// ---------------- scratch (device globals, allocation-free) ----------------
__device__ u16 g_xnh[NROWS * DIMSZ];     // LN out, fp16
__device__ u16 g_wqh[QKVN * DIMSZ];      // Wqkv^T fp16
__device__ u16 g_woh[DIMSZ * DIMSZ];     // Wout^T fp16
__device__ u16 g_qkvh[NROWS * QKVN];     // qkv fp16
__device__ u16 g_vth[BATCH * HEADS * DH * NTOK];   // V^T fp16
__device__ u16 g_atth[NROWS * DIMSZ];    // attention out fp16

// ---------------- helpers ----------------
__device__ __forceinline__ u32 smem_u32(const void* p) {
    u32 a;
    asm("{ .reg .u64 t; cvta.to.shared.u64 t, %1; cvt.u32.u64 %0, t; }" : "=r"(a) : "l"(p));
    return a;
}
__device__ __forceinline__ void ldsm_x4(u32 addr, u32* r) {
    asm volatile("ldmatrix.sync.aligned.m8n8.x4.shared.b16 {%0,%1,%2,%3}, [%4];"
                 : "=r"(r[0]), "=r"(r[1]), "=r"(r[2]), "=r"(r[3]) : "r"(addr));
}
__device__ __forceinline__ void mma16816(float* c, const u32* a, u32 b0, u32 b1) {
    asm volatile("mma.sync.aligned.m16n8k16.row.col.f32.f16.f16.f32 "
                 "{%0,%1,%2,%3}, {%4,%5,%6,%7}, {%8,%9}, {%0,%1,%2,%3};"
                 : "+f"(c[0]), "+f"(c[1]), "+f"(c[2]), "+f"(c[3])
                 : "r"(a[0]), "r"(a[1]), "r"(a[2]), "r"(a[3]), "r"(b0), "r"(b1));
}
#define CP16(dst, src) \
    asm volatile("cp.async.cg.shared.global [%0], [%1], 16;" :: "r"(dst), "l"(src))
#define CP_COMMIT() asm volatile("cp.async.commit_group;" ::: "memory")
#define CP_WAIT0()  asm volatile("cp.async.wait_group 0;" ::: "memory")
#define CP_WAIT1()  asm volatile("cp.async.wait_group 1;" ::: "memory")

__device__ __forceinline__ u32 pack2h(float a, float b) {
    __half2 v = __floats2half2_rn(a, b);
    return *(u32*)&v;
}
__device__ __forceinline__ u16 h16(float a) {
    return __half_as_ushort(__float2half_rn(a));
}

// ===========================================================================
// LayerNorm -> fp16
// ===========================================================================
__global__ __launch_bounds__(256) void ln_kernel(const float* __restrict__ x,
                                                 const float* __restrict__ gamma,
                                                 const float* __restrict__ beta,
                                                 u16* __restrict__ yh) {
    int row = blockIdx.x;
    int t = threadIdx.x;
    __shared__ float sv[DIMSZ];
    __shared__ float sb[8], ssb[8];
    __shared__ float smu, srstd;
    const float* xr = x + (size_t)row * DIMSZ;
    float v0 = xr[t], v1 = xr[t + 256], v2 = xr[t + 512];
    float s = v0 + v1 + v2;
    float ss = v0 * v0 + v1 * v1 + v2 * v2;
#pragma unroll
    for (int o = 16; o > 0; o >>= 1) {
        s += __shfl_xor_sync(0xffffffffu, s, o);
        ss += __shfl_xor_sync(0xffffffffu, ss, o);
    }
    if ((t & 31) == 0) { sb[t >> 5] = s; ssb[t >> 5] = ss; }
    __syncthreads();
    if (t == 0) {
        float S = 0.f, SS = 0.f;
#pragma unroll
        for (int i = 0; i < 8; i++) { S += sb[i]; SS += ssb[i]; }
        float mu = S * (1.0f / DIMSZ);
        float var = SS * (1.0f / DIMSZ) - mu * mu;
        smu = mu;
        srstd = rsqrtf(var + 1e-5f);
    }
    __syncthreads();
    float mu = smu, rstd = srstd;
    sv[t]       = (v0 - mu) * rstd * gamma[t]       + beta[t];
    sv[t + 256] = (v1 - mu) * rstd * gamma[t + 256] + beta[t + 256];
    sv[t + 512] = (v2 - mu) * rstd * gamma[t + 512] + beta[t + 512];
    __syncthreads();
    u32* oh = (u32*)(yh + (size_t)row * DIMSZ);
    for (int p = t; p < DIMSZ / 2; p += 256)
        oh[p] = pack2h(sv[2 * p], sv[2 * p + 1]);
}

// ===========================================================================
// Weight transpose to fp16 (both weights in one launch, z selects)
// ===========================================================================
__global__ __launch_bounds__(256) void wprep_kernel(const float* __restrict__ Wq,
                                                    const float* __restrict__ Wo,
                                                    u16* __restrict__ Wqt,
                                                    u16* __restrict__ Wot) {
    const float* W;
    u16* Wt;
    int Nsz;
    if (blockIdx.z == 0) { W = Wq; Wt = Wqt; Nsz = QKVN; }
    else {
        if (blockIdx.x >= DIMSZ / 32) return;
        W = Wo; Wt = Wot; Nsz = DIMSZ;
    }
    __shared__ float sm[32][33];
    int tx = threadIdx.x & 31, ty = threadIdx.x >> 5;   // 32 x 8
    int n0 = blockIdx.x * 32, k0 = blockIdx.y * 32;
#pragma unroll
    for (int i = 0; i < 4; i++)
        sm[ty + i * 8][tx] = W[(size_t)(k0 + ty + i * 8) * Nsz + n0 + tx];
    __syncthreads();
#pragma unroll
    for (int i = 0; i < 4; i++) {
        int n = n0 + ty + i * 8, k = k0 + tx;
        Wt[(size_t)n * DIMSZ + k] = h16(sm[tx][ty + i * 8]);
    }
}

// ===========================================================================
// V transpose: qkv V part [b][j][h*64+d] -> vt [b][h][d][j]
// ===========================================================================
__global__ __launch_bounds__(256) void vtrans_kernel(const u16* __restrict__ qh,
                                                     u16* __restrict__ vh) {
    __shared__ u16 sm[64][66];
    int t = threadIdx.x;
    int j0 = blockIdx.x * 64, h = blockIdx.y, b = blockIdx.z;
#pragma unroll
    for (int i = 0; i < 8; i++) {
        int id = t + i * 256;          // 0..2047
        int jj = id >> 5, dp = id & 31;
        u32 v = *(const u32*)(qh + (size_t)(b * NTOK + j0 + jj) * QKVN +
                              2 * DIMSZ + h * DH + dp * 2);
        sm[jj][2 * dp] = (u16)v;
        sm[jj][2 * dp + 1] = (u16)(v >> 16);
    }
    __syncthreads();
#pragma unroll
    for (int i = 0; i < 8; i++) {
        int id = t + i * 256;
        int d = id >> 5, jp = id & 31;
        u32 v = (u32)sm[2 * jp][d] | ((u32)sm[2 * jp + 1][d] << 16);
        *(u32*)(vh + ((size_t)((b * HEADS + h) * DH + d)) * NTOK + j0 + 2 * jp) = v;
    }
}

// ===========================================================================
// fp16 1-term GEMM: C[M,N] = A[M,768] @ B[N,768]^T (+bias)
// CTA 128x128, 512 thr (16 warps, 32x32 tiles), KC=64, NBUF=3 cp.async.
// EPI 0: fp32 out + bias.  EPI 1: fp16 out, SCALE folded on n<768.
// ===========================================================================
#define TROW 144                  /* 64 fp16 (128B) + 16B pad */
#define TILE (128 * TROW)         /* 18432 */
#define STAGE (2 * TILE)          /* 36864: A, B */
#define NBUF 3
#define GEMM_SMEM (NBUF * STAGE)  /* 110592 */
#define KC 64
#define NSTAGE (DIMSZ / KC)       /* 12 */
#define B_OFF TILE

template <int EPI>
__global__ __launch_bounds__(512, 1) void mma_gemm(const u16* __restrict__ Ah,
                                                   const u16* __restrict__ Bh,
                                                   const float* __restrict__ bias,
                                                   float* __restrict__ Cf,
                                                   u16* __restrict__ Ch,
                                                   int Nsz) {
    extern __shared__ char smem[];
    const u32 smb = smem_u32(smem);
    const int t = threadIdx.x;
    const int wid = t >> 5, lane = t & 31;
    const int m0 = blockIdx.y * 128, n0 = blockIdx.x * 128;
    const int wm = (wid >> 2) * 32, wn = (wid & 3) * 32;

    float acc[2][4][4];
#pragma unroll
    for (int i = 0; i < 2; i++)
#pragma unroll
        for (int j = 0; j < 4; j++)
#pragma unroll
            for (int k = 0; k < 4; k++) acc[i][j][k] = 0.f;

    const int frow = t >> 2;          // 0..127
    const int q4 = t & 3;             // 16-elem quarter

    auto fill = [&](int c) {
        const u32 base = smb + (c % NBUF) * STAGE;
        const size_t aoff = (size_t)(m0 + frow) * DIMSZ + c * KC + q4 * 16;
        const size_t boff = (size_t)(n0 + frow) * DIMSZ + c * KC + q4 * 16;
        const u32 doff = (u32)(frow * TROW + q4 * 32);
        CP16(base + doff, Ah + aoff);
        CP16(base + doff + 16, Ah + aoff + 8);
        CP16(base + B_OFF + doff, Bh + boff);
        CP16(base + B_OFF + doff + 16, Bh + boff + 8);
    };

    const int brow = ((lane >> 4) << 3) + (lane & 7);

    auto compute = [&](int c) {
        const u32 base = smb + (c % NBUF) * STAGE;
#pragma unroll
        for (int ks = 0; ks < 4; ks++) {
            u32 Ahf[2][4], Bhf[2][4];
            const u32 akb = (u32)(ks * 32 + ((lane & 16) ? 16 : 0));
#pragma unroll
            for (int mt = 0; mt < 2; mt++) {
                u32 ra = base + (u32)((wm + mt * 16 + (lane & 15)) * TROW) + akb;
                ldsm_x4(ra, Ahf[mt]);
            }
            const u32 bkb = (u32)(ks * 32 + ((lane & 8) ? 16 : 0));
#pragma unroll
            for (int bt = 0; bt < 2; bt++) {
                u32 rb = base + B_OFF + (u32)((wn + bt * 16 + brow) * TROW) + bkb;
                ldsm_x4(rb, Bhf[bt]);
            }
#pragma unroll
            for (int mt = 0; mt < 2; mt++)
#pragma unroll
                for (int nt = 0; nt < 4; nt++)
                    mma16816(acc[mt][nt], Ahf[mt],
                             Bhf[nt >> 1][(nt & 1) * 2], Bhf[nt >> 1][(nt & 1) * 2 + 1]);
        }
    };

    fill(0); CP_COMMIT();
    fill(1); CP_COMMIT();
    for (int c = 0; c < NSTAGE; c++) {
        CP_WAIT1();
        __syncthreads();
        if (c + 2 < NSTAGE) fill(c + 2);
        CP_COMMIT();
        compute(c);
    }

    // epilogue
#pragma unroll
    for (int mt = 0; mt < 2; mt++) {
        int m = m0 + wm + mt * 16 + (lane >> 2);
#pragma unroll
        for (int nt = 0; nt < 4; nt++) {
            int n = n0 + wn + nt * 8 + (lane & 3) * 2;
            if (EPI == 0) {
                float bx = bias[n], by = bias[n + 1];
                *(float2*)&Cf[(size_t)m * Nsz + n] =
                    make_float2(acc[mt][nt][0] + bx, acc[mt][nt][1] + by);
                *(float2*)&Cf[(size_t)(m + 8) * Nsz + n] =
                    make_float2(acc[mt][nt][2] + bx, acc[mt][nt][3] + by);
            } else {
                float sc = (n < DIMSZ) ? SCALE : 1.0f;
                *(u32*)(Ch + (size_t)m * Nsz + n) =
                    pack2h(acc[mt][nt][0] * sc, acc[mt][nt][1] * sc);
                *(u32*)(Ch + (size_t)(m + 8) * Nsz + n) =
                    pack2h(acc[mt][nt][2] * sc, acc[mt][nt][3] * sc);
            }
        }
    }
}

// ===========================================================================
// Attention, all 1-term fp16: S = Q K^T,  O = P V.  (R11/R13-proven version)
// Block = 256 thr (8 warps), one (b,h,128-q-row tile). K/V cp.async double-buf.
// ===========================================================================
#define AROW 144
#define QTILE (128 * AROW)          /* 18432 (hi only) */
#define KTILE (64 * AROW)           /* 9216 */
#define AKVB (2 * KTILE)            /* Kh,Vh = 18432 */
#define ASMEM (QTILE + 2 * AKVB)    /* 55296; x2 CTAs = 110592 */

__global__ __launch_bounds__(256, 2) void attn_mma(const u16* __restrict__ qh,
                                                   const u16* __restrict__ vth,
                                                   const float* __restrict__ rpb,
                                                   u16* __restrict__ oh) {
    extern __shared__ char smem[];
    const u32 smb = smem_u32(smem);
    const int t = threadIdx.x;
    const int w = t >> 5, lane = t & 31;
    const int i0 = blockIdx.x * 128, h = blockIdx.y, b = blockIdx.z;

    const int brow = ((lane >> 4) << 3) + (lane & 7);

    // ---- Q tile (128 rows) -> smem ----
    {
        const int frow = t >> 1, half = t & 1;
        const size_t qoff = (size_t)(b * NTOK + i0 + frow) * QKVN + h * DH + half * 32;
        const u32 doff = (u32)(frow * AROW + half * 64);
#pragma unroll
        for (int i = 0; i < 4; i++)
            CP16(smb + doff + i * 16, qh + qoff + i * 8);
        CP_COMMIT();
    }

    auto fillKV = [&](int jt) {
        const u32 base = smb + QTILE + (jt & 1) * AKVB;
        const int row = t >> 2, q4 = t & 3;
        const size_t koff = (size_t)(b * NTOK + jt * 64 + row) * QKVN + DIMSZ + h * DH + q4 * 16;
        const size_t voff = (size_t)((b * HEADS + h) * DH + row) * NTOK + jt * 64 + q4 * 16;
        const u32 doff = (u32)(row * AROW + q4 * 32);
        CP16(base + doff, qh + koff);
        CP16(base + doff + 16, qh + koff + 8);
        CP16(base + KTILE + doff, vth + voff);
        CP16(base + KTILE + doff + 16, vth + voff + 8);
    };

    fillKV(0); CP_COMMIT();

    CP_WAIT1();
    __syncthreads();
    u32 Aqh[4][4];
#pragma unroll
    for (int ks = 0; ks < 4; ks++) {
        u32 ra = smb + (u32)((w * 16 + (lane & 15)) * AROW) + ks * 32 + ((lane & 16) ? 16 : 0);
        ldsm_x4(ra, Aqh[ks]);
    }

    float o[8][4];
#pragma unroll
    for (int nt = 0; nt < 8; nt++)
#pragma unroll
        for (int k = 0; k < 4; k++) o[nt][k] = 0.f;
    float mA = -1e30f, mB = -1e30f, lA = 0.f, lB = 0.f;

    const float* bp = rpb + ((size_t)(h * NTOK + i0 + w * 16 + (lane >> 2))) * NTOK + 2 * (lane & 3);

    for (int jt = 0; jt < 16; jt++) {
        CP_WAIT0();
        __syncthreads();
        if (jt + 1 < 16) { fillKV(jt + 1); CP_COMMIT(); }

        const u32 kb = smb + QTILE + (jt & 1) * AKVB;
        const u32 vb = kb + KTILE;

        // ---- S = Q K^T (1-term) ----
        float s[8][4];
#pragma unroll
        for (int nt = 0; nt < 8; nt++)
#pragma unroll
            for (int k = 0; k < 4; k++) s[nt][k] = 0.f;
#pragma unroll
        for (int ks = 0; ks < 4; ks++) {
            u32 Bf[4][4];
            const u32 bkb = (u32)(ks * 32 + ((lane & 8) ? 16 : 0));
#pragma unroll
            for (int bt = 0; bt < 4; bt++) {
                u32 rb = kb + (u32)((bt * 16 + brow) * AROW) + bkb;
                ldsm_x4(rb, Bf[bt]);
            }
#pragma unroll
            for (int nt = 0; nt < 8; nt++)
                mma16816(s[nt], Aqh[ks],
                         Bf[nt >> 1][(nt & 1) * 2], Bf[nt >> 1][(nt & 1) * 2 + 1]);
        }

        // ---- + bias, online softmax ----
        const float* bpj = bp + jt * 64;
        float tmA = -1e30f, tmB = -1e30f;
#pragma unroll
        for (int nt = 0; nt < 8; nt++) {
            float2 ba = *(const float2*)(bpj + nt * 8);
            float2 bb = *(const float2*)(bpj + 8 * NTOK + nt * 8);
            s[nt][0] += ba.x; s[nt][1] += ba.y;
            s[nt][2] += bb.x; s[nt][3] += bb.y;
            tmA = fmaxf(tmA, fmaxf(s[nt][0], s[nt][1]));
            tmB = fmaxf(tmB, fmaxf(s[nt][2], s[nt][3]));
        }
        tmA = fmaxf(tmA, __shfl_xor_sync(0xffffffffu, tmA, 1));
        tmA = fmaxf(tmA, __shfl_xor_sync(0xffffffffu, tmA, 2));
        tmB = fmaxf(tmB, __shfl_xor_sync(0xffffffffu, tmB, 1));
        tmB = fmaxf(tmB, __shfl_xor_sync(0xffffffffu, tmB, 2));
        float nmA = fmaxf(mA, tmA), nmB = fmaxf(mB, tmB);
        float facA = __expf(mA - nmA), facB = __expf(mB - nmB);
        mA = nmA; mB = nmB;
        float suA = 0.f, suB = 0.f;
#pragma unroll
        for (int nt = 0; nt < 8; nt++) {
            s[nt][0] = __expf(s[nt][0] - mA);
            s[nt][1] = __expf(s[nt][1] - mA);
            s[nt][2] = __expf(s[nt][2] - mB);
            s[nt][3] = __expf(s[nt][3] - mB);
            suA += s[nt][0] + s[nt][1];
            suB += s[nt][2] + s[nt][3];
            o[nt][0] *= facA; o[nt][1] *= facA;
            o[nt][2] *= facB; o[nt][3] *= facB;
        }
        suA += __shfl_xor_sync(0xffffffffu, suA, 1);
        suA += __shfl_xor_sync(0xffffffffu, suA, 2);
        suB += __shfl_xor_sync(0xffffffffu, suB, 1);
        suB += __shfl_xor_sync(0xffffffffu, suB, 2);
        lA = lA * facA + suA;
        lB = lB * facB + suB;

        // ---- P fragments (fp16) ----
        u32 Aph[4][4];
#pragma unroll
        for (int kt = 0; kt < 4; kt++) {
            Aph[kt][0] = pack2h(s[2 * kt][0], s[2 * kt][1]);
            Aph[kt][1] = pack2h(s[2 * kt][2], s[2 * kt][3]);
            Aph[kt][2] = pack2h(s[2 * kt + 1][0], s[2 * kt + 1][1]);
            Aph[kt][3] = pack2h(s[2 * kt + 1][2], s[2 * kt + 1][3]);
        }

        // ---- O += P V (1-term), V^T in smem [d][j] ----
#pragma unroll
        for (int kt = 0; kt < 4; kt++) {
            u32 Bf[4][4];
            const u32 bkb = (u32)(kt * 32 + ((lane & 8) ? 16 : 0));
#pragma unroll
            for (int bt = 0; bt < 4; bt++) {
                u32 rb = vb + (u32)((bt * 16 + brow) * AROW) + bkb;
                ldsm_x4(rb, Bf[bt]);
            }
#pragma unroll
            for (int nt = 0; nt < 8; nt++)
                mma16816(o[nt], Aph[kt],
                         Bf[nt >> 1][(nt & 1) * 2], Bf[nt >> 1][(nt & 1) * 2 + 1]);
        }
    }

    // ---- epilogue: normalize, store fp16 ----
    float invA = 1.0f / lA, invB = 1.0f / lB;
    int rowA = b * NTOK + i0 + w * 16 + (lane >> 2);
#pragma unroll
    for (int nt = 0; nt < 8; nt++) {
        int col = h * DH + nt * 8 + 2 * (lane & 3);
        *(u32*)(oh + (size_t)rowA * DIMSZ + col) = pack2h(o[nt][0] * invA, o[nt][1] * invA);
        *(u32*)(oh + (size_t)(rowA + 8) * DIMSZ + col) = pack2h(o[nt][2] * invB, o[nt][3] * invB);
    }
}

// ---------------------------------------------------------------------------
extern "C" void kernel_launch(void* const* d_in, const int* in_sizes, int n_in,
                              void* d_out, int out_size) {
    const float* x    = (const float*)d_in[0];
    const float* rpb  = (const float*)d_in[1];
    const float* Wqkv = (const float*)d_in[2];
    const float* Wout = (const float*)d_in[3];
    const float* bout = (const float*)d_in[4];
    const float* lng  = (const float*)d_in[5];
    const float* lnb  = (const float*)d_in[6];
    float* out = (float*)d_out;

    u16 *xnh, *wqh, *woh, *qkh, *vth, *ath;
    cudaGetSymbolAddress((void**)&xnh, g_xnh);
    cudaGetSymbolAddress((void**)&wqh, g_wqh);
    cudaGetSymbolAddress((void**)&woh, g_woh);
    cudaGetSymbolAddress((void**)&qkh, g_qkvh);
    cudaGetSymbolAddress((void**)&vth, g_vth);
    cudaGetSymbolAddress((void**)&ath, g_atth);

    // 1) LN -> fp16
    ln_kernel<<<NROWS, 256>>>(x, lng, lnb, xnh);

    // 1b) weight prep (both weights, one launch)
    wprep_kernel<<<dim3(QKVN / 32, DIMSZ / 32, 2), 256>>>(Wqkv, Wout, wqh, woh);

    // 2) QKV projection (1-term, fp16 out, Q pre-scaled)
    cudaFuncSetAttribute(mma_gemm<1>, cudaFuncAttributeMaxDynamicSharedMemorySize, GEMM_SMEM);
    mma_gemm<1><<<dim3(QKVN / 128, NROWS / 128), 512, GEMM_SMEM>>>(
        xnh, wqh, nullptr, nullptr, qkh, QKVN);

    // 2b) V transpose
    vtrans_kernel<<<dim3(NTOK / 64, HEADS, BATCH), 256>>>(qkh, vth);

    // 3) attention (all 1-term fp16)
    cudaFuncSetAttribute(attn_mma, cudaFuncAttributeMaxDynamicSharedMemorySize, ASMEM);
    attn_mma<<<dim3(NTOK / 128, HEADS, BATCH), 256, ASMEM>>>(
        qkh, vth, rpb, ath);

    // 4) output projection (1-term, fp32 out + bias)
    cudaFuncSetAttribute(mma_gemm<0>, cudaFuncAttributeMaxDynamicSharedMemorySize, GEMM_SMEM);
    mma_gemm<0><<<dim3(DIMSZ / 128, NROWS / 128), 512, GEMM_SMEM>>>(
        ath, woh, bout, out, nullptr, DIMSZ);
}

// round 17
// speedup vs baseline: 1.5819x; 1.0051x over previous
#include <cuda_runtime.h>
#include <cuda_fp16.h>
#include <cstdint>

#define DIMSZ 768
#define NTOK 1024
#define BATCH 8
#define HEADS 12
#define DH 64
#define NROWS (BATCH * NTOK)      /* 8192 */
#define QKVN (3 * DIMSZ)          /* 2304 */
#define SCALE 0.125f              /* DH^-0.5 */

typedef unsigned short u16;
typedef uint32_t u32;

// ---------------- scratch (device globals, allocation-free) ----------------
__device__ u16 g_xnh[NROWS * DIMSZ];     // LN out, fp16
__device__ u16 g_wqh[QKVN * DIMSZ];      // Wqkv^T fp16
__device__ u16 g_woh[DIMSZ * DIMSZ];     // Wout^T fp16
__device__ u16 g_qkvh[NROWS * QKVN];     // qkv fp16
__device__ u16 g_vth[BATCH * HEADS * DH * NTOK];   // V^T fp16
__device__ u16 g_atth[NROWS * DIMSZ];    // attention out fp16

// ---------------- helpers ----------------
__device__ __forceinline__ u32 smem_u32(const void* p) {
    u32 a;
    asm("{ .reg .u64 t; cvta.to.shared.u64 t, %1; cvt.u32.u64 %0, t; }" : "=r"(a) : "l"(p));
    return a;
}
__device__ __forceinline__ void ldsm_x4(u32 addr, u32* r) {
    asm volatile("ldmatrix.sync.aligned.m8n8.x4.shared.b16 {%0,%1,%2,%3}, [%4];"
                 : "=r"(r[0]), "=r"(r[1]), "=r"(r[2]), "=r"(r[3]) : "r"(addr));
}
__device__ __forceinline__ void mma16816(float* c, const u32* a, u32 b0, u32 b1) {
    asm volatile("mma.sync.aligned.m16n8k16.row.col.f32.f16.f16.f32 "
                 "{%0,%1,%2,%3}, {%4,%5,%6,%7}, {%8,%9}, {%0,%1,%2,%3};"
                 : "+f"(c[0]), "+f"(c[1]), "+f"(c[2]), "+f"(c[3])
                 : "r"(a[0]), "r"(a[1]), "r"(a[2]), "r"(a[3]), "r"(b0), "r"(b1));
}
#define CP16(dst, src) \
    asm volatile("cp.async.cg.shared.global [%0], [%1], 16;" :: "r"(dst), "l"(src))
#define CP_COMMIT() asm volatile("cp.async.commit_group;" ::: "memory")
#define CP_WAIT0()  asm volatile("cp.async.wait_group 0;" ::: "memory")
#define CP_WAIT1()  asm volatile("cp.async.wait_group 1;" ::: "memory")

__device__ __forceinline__ u32 pack2h(float a, float b) {
    __half2 v = __floats2half2_rn(a, b);
    return *(u32*)&v;
}
__device__ __forceinline__ u16 h16(float a) {
    return __half_as_ushort(__float2half_rn(a));
}

// ===========================================================================
// LayerNorm -> fp16
// ===========================================================================
__global__ __launch_bounds__(256) void ln_kernel(const float* __restrict__ x,
                                                 const float* __restrict__ gamma,
                                                 const float* __restrict__ beta,
                                                 u16* __restrict__ yh) {
    int row = blockIdx.x;
    int t = threadIdx.x;
    __shared__ float sv[DIMSZ];
    __shared__ float sb[8], ssb[8];
    __shared__ float smu, srstd;
    const float* xr = x + (size_t)row * DIMSZ;
    float v0 = xr[t], v1 = xr[t + 256], v2 = xr[t + 512];
    float s = v0 + v1 + v2;
    float ss = v0 * v0 + v1 * v1 + v2 * v2;
#pragma unroll
    for (int o = 16; o > 0; o >>= 1) {
        s += __shfl_xor_sync(0xffffffffu, s, o);
        ss += __shfl_xor_sync(0xffffffffu, ss, o);
    }
    if ((t & 31) == 0) { sb[t >> 5] = s; ssb[t >> 5] = ss; }
    __syncthreads();
    if (t == 0) {
        float S = 0.f, SS = 0.f;
#pragma unroll
        for (int i = 0; i < 8; i++) { S += sb[i]; SS += ssb[i]; }
        float mu = S * (1.0f / DIMSZ);
        float var = SS * (1.0f / DIMSZ) - mu * mu;
        smu = mu;
        srstd = rsqrtf(var + 1e-5f);
    }
    __syncthreads();
    float mu = smu, rstd = srstd;
    sv[t]       = (v0 - mu) * rstd * gamma[t]       + beta[t];
    sv[t + 256] = (v1 - mu) * rstd * gamma[t + 256] + beta[t + 256];
    sv[t + 512] = (v2 - mu) * rstd * gamma[t + 512] + beta[t + 512];
    __syncthreads();
    u32* oh = (u32*)(yh + (size_t)row * DIMSZ);
    for (int p = t; p < DIMSZ / 2; p += 256)
        oh[p] = pack2h(sv[2 * p], sv[2 * p + 1]);
}

// ===========================================================================
// Weight transpose to fp16 (both weights in one launch, z selects)
// ===========================================================================
__global__ __launch_bounds__(256) void wprep_kernel(const float* __restrict__ Wq,
                                                    const float* __restrict__ Wo,
                                                    u16* __restrict__ Wqt,
                                                    u16* __restrict__ Wot) {
    const float* W;
    u16* Wt;
    int Nsz;
    if (blockIdx.z == 0) { W = Wq; Wt = Wqt; Nsz = QKVN; }
    else {
        if (blockIdx.x >= DIMSZ / 32) return;
        W = Wo; Wt = Wot; Nsz = DIMSZ;
    }
    __shared__ float sm[32][33];
    int tx = threadIdx.x & 31, ty = threadIdx.x >> 5;   // 32 x 8
    int n0 = blockIdx.x * 32, k0 = blockIdx.y * 32;
#pragma unroll
    for (int i = 0; i < 4; i++)
        sm[ty + i * 8][tx] = W[(size_t)(k0 + ty + i * 8) * Nsz + n0 + tx];
    __syncthreads();
#pragma unroll
    for (int i = 0; i < 4; i++) {
        int n = n0 + ty + i * 8, k = k0 + tx;
        Wt[(size_t)n * DIMSZ + k] = h16(sm[tx][ty + i * 8]);
    }
}

// ===========================================================================
// V transpose: qkv V part [b][j][h*64+d] -> vt [b][h][d][j]
// ===========================================================================
__global__ __launch_bounds__(256) void vtrans_kernel(const u16* __restrict__ qh,
                                                     u16* __restrict__ vh) {
    __shared__ u16 sm[64][66];
    int t = threadIdx.x;
    int j0 = blockIdx.x * 64, h = blockIdx.y, b = blockIdx.z;
#pragma unroll
    for (int i = 0; i < 8; i++) {
        int id = t + i * 256;          // 0..2047
        int jj = id >> 5, dp = id & 31;
        u32 v = *(const u32*)(qh + (size_t)(b * NTOK + j0 + jj) * QKVN +
                              2 * DIMSZ + h * DH + dp * 2);
        sm[jj][2 * dp] = (u16)v;
        sm[jj][2 * dp + 1] = (u16)(v >> 16);
    }
    __syncthreads();
#pragma unroll
    for (int i = 0; i < 8; i++) {
        int id = t + i * 256;
        int d = id >> 5, jp = id & 31;
        u32 v = (u32)sm[2 * jp][d] | ((u32)sm[2 * jp + 1][d] << 16);
        *(u32*)(vh + ((size_t)((b * HEADS + h) * DH + d)) * NTOK + j0 + 2 * jp) = v;
    }
}

// ===========================================================================
// fp16 1-term GEMM: C[M,N] = A[M,768] @ B[N,768]^T (+bias)
// CTA 128x128, 512 thr (16 warps, 32x32 tiles), KC=64, NBUF=3 cp.async.
// EPI 0: fp32 out + bias.  EPI 1: fp16 out, SCALE folded on n<768.
// ===========================================================================
#define TROW 144                  /* 64 fp16 (128B) + 16B pad */
#define TILE (128 * TROW)         /* 18432 */
#define STAGE (2 * TILE)          /* 36864: A, B */
#define NBUF 3
#define GEMM_SMEM (NBUF * STAGE)  /* 110592 */
#define KC 64
#define NSTAGE (DIMSZ / KC)       /* 12 */
#define B_OFF TILE

template <int EPI>
__global__ __launch_bounds__(512, 1) void mma_gemm(const u16* __restrict__ Ah,
                                                   const u16* __restrict__ Bh,
                                                   const float* __restrict__ bias,
                                                   float* __restrict__ Cf,
                                                   u16* __restrict__ Ch,
                                                   int Nsz) {
    extern __shared__ char smem[];
    const u32 smb = smem_u32(smem);
    const int t = threadIdx.x;
    const int wid = t >> 5, lane = t & 31;
    const int m0 = blockIdx.y * 128, n0 = blockIdx.x * 128;
    const int wm = (wid >> 2) * 32, wn = (wid & 3) * 32;

    float acc[2][4][4];
#pragma unroll
    for (int i = 0; i < 2; i++)
#pragma unroll
        for (int j = 0; j < 4; j++)
#pragma unroll
            for (int k = 0; k < 4; k++) acc[i][j][k] = 0.f;

    const int frow = t >> 2;          // 0..127
    const int q4 = t & 3;             // 16-elem quarter

    auto fill = [&](int c) {
        const u32 base = smb + (c % NBUF) * STAGE;
        const size_t aoff = (size_t)(m0 + frow) * DIMSZ + c * KC + q4 * 16;
        const size_t boff = (size_t)(n0 + frow) * DIMSZ + c * KC + q4 * 16;
        const u32 doff = (u32)(frow * TROW + q4 * 32);
        CP16(base + doff, Ah + aoff);
        CP16(base + doff + 16, Ah + aoff + 8);
        CP16(base + B_OFF + doff, Bh + boff);
        CP16(base + B_OFF + doff + 16, Bh + boff + 8);
    };

    const int brow = ((lane >> 4) << 3) + (lane & 7);

    auto compute = [&](int c) {
        const u32 base = smb + (c % NBUF) * STAGE;
#pragma unroll
        for (int ks = 0; ks < 4; ks++) {
            u32 Ahf[2][4], Bhf[2][4];
            const u32 akb = (u32)(ks * 32 + ((lane & 16) ? 16 : 0));
#pragma unroll
            for (int mt = 0; mt < 2; mt++) {
                u32 ra = base + (u32)((wm + mt * 16 + (lane & 15)) * TROW) + akb;
                ldsm_x4(ra, Ahf[mt]);
            }
            const u32 bkb = (u32)(ks * 32 + ((lane & 8) ? 16 : 0));
#pragma unroll
            for (int bt = 0; bt < 2; bt++) {
                u32 rb = base + B_OFF + (u32)((wn + bt * 16 + brow) * TROW) + bkb;
                ldsm_x4(rb, Bhf[bt]);
            }
#pragma unroll
            for (int mt = 0; mt < 2; mt++)
#pragma unroll
                for (int nt = 0; nt < 4; nt++)
                    mma16816(acc[mt][nt], Ahf[mt],
                             Bhf[nt >> 1][(nt & 1) * 2], Bhf[nt >> 1][(nt & 1) * 2 + 1]);
        }
    };

    fill(0); CP_COMMIT();
    fill(1); CP_COMMIT();
    for (int c = 0; c < NSTAGE; c++) {
        CP_WAIT1();
        __syncthreads();
        if (c + 2 < NSTAGE) fill(c + 2);
        CP_COMMIT();
        compute(c);
    }

    // epilogue
#pragma unroll
    for (int mt = 0; mt < 2; mt++) {
        int m = m0 + wm + mt * 16 + (lane >> 2);
#pragma unroll
        for (int nt = 0; nt < 4; nt++) {
            int n = n0 + wn + nt * 8 + (lane & 3) * 2;
            if (EPI == 0) {
                float bx = bias[n], by = bias[n + 1];
                *(float2*)&Cf[(size_t)m * Nsz + n] =
                    make_float2(acc[mt][nt][0] + bx, acc[mt][nt][1] + by);
                *(float2*)&Cf[(size_t)(m + 8) * Nsz + n] =
                    make_float2(acc[mt][nt][2] + bx, acc[mt][nt][3] + by);
            } else {
                float sc = (n < DIMSZ) ? SCALE : 1.0f;
                *(u32*)(Ch + (size_t)m * Nsz + n) =
                    pack2h(acc[mt][nt][0] * sc, acc[mt][nt][1] * sc);
                *(u32*)(Ch + (size_t)(m + 8) * Nsz + n) =
                    pack2h(acc[mt][nt][2] * sc, acc[mt][nt][3] * sc);
            }
        }
    }
}

// ===========================================================================
// Attention, all 1-term fp16: S = Q K^T,  O = P V.
// R13 structure; single change: rpb bias loads hoisted ABOVE the S-MMA loop
// so their L2 latency hides under the QK^T MMAs.
// ===========================================================================
#define AROW 144
#define QTILE (128 * AROW)          /* 18432 (hi only) */
#define KTILE (64 * AROW)           /* 9216 */
#define AKVB (2 * KTILE)            /* Kh,Vh = 18432 */
#define ASMEM (QTILE + 2 * AKVB)    /* 55296; x2 CTAs = 110592 */

__global__ __launch_bounds__(256, 2) void attn_mma(const u16* __restrict__ qh,
                                                   const u16* __restrict__ vth,
                                                   const float* __restrict__ rpb,
                                                   u16* __restrict__ oh) {
    extern __shared__ char smem[];
    const u32 smb = smem_u32(smem);
    const int t = threadIdx.x;
    const int w = t >> 5, lane = t & 31;
    const int i0 = blockIdx.x * 128, h = blockIdx.y, b = blockIdx.z;

    const int brow = ((lane >> 4) << 3) + (lane & 7);

    // ---- Q tile (128 rows) -> smem ----
    {
        const int frow = t >> 1, half = t & 1;
        const size_t qoff = (size_t)(b * NTOK + i0 + frow) * QKVN + h * DH + half * 32;
        const u32 doff = (u32)(frow * AROW + half * 64);
#pragma unroll
        for (int i = 0; i < 4; i++)
            CP16(smb + doff + i * 16, qh + qoff + i * 8);
        CP_COMMIT();
    }

    auto fillKV = [&](int jt) {
        const u32 base = smb + QTILE + (jt & 1) * AKVB;
        const int row = t >> 2, q4 = t & 3;
        const size_t koff = (size_t)(b * NTOK + jt * 64 + row) * QKVN + DIMSZ + h * DH + q4 * 16;
        const size_t voff = (size_t)((b * HEADS + h) * DH + row) * NTOK + jt * 64 + q4 * 16;
        const u32 doff = (u32)(row * AROW + q4 * 32);
        CP16(base + doff, qh + koff);
        CP16(base + doff + 16, qh + koff + 8);
        CP16(base + KTILE + doff, vth + voff);
        CP16(base + KTILE + doff + 16, vth + voff + 8);
    };

    fillKV(0); CP_COMMIT();

    CP_WAIT1();
    __syncthreads();
    u32 Aqh[4][4];
#pragma unroll
    for (int ks = 0; ks < 4; ks++) {
        u32 ra = smb + (u32)((w * 16 + (lane & 15)) * AROW) + ks * 32 + ((lane & 16) ? 16 : 0);
        ldsm_x4(ra, Aqh[ks]);
    }

    float o[8][4];
#pragma unroll
    for (int nt = 0; nt < 8; nt++)
#pragma unroll
        for (int k = 0; k < 4; k++) o[nt][k] = 0.f;
    float mA = -1e30f, mB = -1e30f, lA = 0.f, lB = 0.f;

    const float* bp = rpb + ((size_t)(h * NTOK + i0 + w * 16 + (lane >> 2))) * NTOK + 2 * (lane & 3);

    for (int jt = 0; jt < 16; jt++) {
        CP_WAIT0();
        __syncthreads();
        if (jt + 1 < 16) { fillKV(jt + 1); CP_COMMIT(); }

        const u32 kb = smb + QTILE + (jt & 1) * AKVB;
        const u32 vb = kb + KTILE;

        // ---- bias prefetch (independent of S; hides L2 latency under MMAs) ----
        const float* bpj = bp + jt * 64;
        float2 ba[8], bb[8];
#pragma unroll
        for (int nt = 0; nt < 8; nt++) {
            ba[nt] = *(const float2*)(bpj + nt * 8);
            bb[nt] = *(const float2*)(bpj + 8 * NTOK + nt * 8);
        }

        // ---- S = Q K^T (1-term) ----
        float s[8][4];
#pragma unroll
        for (int nt = 0; nt < 8; nt++)
#pragma unroll
            for (int k = 0; k < 4; k++) s[nt][k] = 0.f;
#pragma unroll
        for (int ks = 0; ks < 4; ks++) {
            u32 Bf[4][4];
            const u32 bkb = (u32)(ks * 32 + ((lane & 8) ? 16 : 0));
#pragma unroll
            for (int bt = 0; bt < 4; bt++) {
                u32 rb = kb + (u32)((bt * 16 + brow) * AROW) + bkb;
                ldsm_x4(rb, Bf[bt]);
            }
#pragma unroll
            for (int nt = 0; nt < 8; nt++)
                mma16816(s[nt], Aqh[ks],
                         Bf[nt >> 1][(nt & 1) * 2], Bf[nt >> 1][(nt & 1) * 2 + 1]);
        }

        // ---- + bias, online softmax ----
        float tmA = -1e30f, tmB = -1e30f;
#pragma unroll
        for (int nt = 0; nt < 8; nt++) {
            s[nt][0] += ba[nt].x; s[nt][1] += ba[nt].y;
            s[nt][2] += bb[nt].x; s[nt][3] += bb[nt].y;
            tmA = fmaxf(tmA, fmaxf(s[nt][0], s[nt][1]));
            tmB = fmaxf(tmB, fmaxf(s[nt][2], s[nt][3]));
        }
        tmA = fmaxf(tmA, __shfl_xor_sync(0xffffffffu, tmA, 1));
        tmA = fmaxf(tmA, __shfl_xor_sync(0xffffffffu, tmA, 2));
        tmB = fmaxf(tmB, __shfl_xor_sync(0xffffffffu, tmB, 1));
        tmB = fmaxf(tmB, __shfl_xor_sync(0xffffffffu, tmB, 2));
        float nmA = fmaxf(mA, tmA), nmB = fmaxf(mB, tmB);
        float facA = __expf(mA - nmA), facB = __expf(mB - nmB);
        mA = nmA; mB = nmB;
        float suA = 0.f, suB = 0.f;
#pragma unroll
        for (int nt = 0; nt < 8; nt++) {
            s[nt][0] = __expf(s[nt][0] - mA);
            s[nt][1] = __expf(s[nt][1] - mA);
            s[nt][2] = __expf(s[nt][2] - mB);
            s[nt][3] = __expf(s[nt][3] - mB);
            suA += s[nt][0] + s[nt][1];
            suB += s[nt][2] + s[nt][3];
            o[nt][0] *= facA; o[nt][1] *= facA;
            o[nt][2] *= facB; o[nt][3] *= facB;
        }
        suA += __shfl_xor_sync(0xffffffffu, suA, 1);
        suA += __shfl_xor_sync(0xffffffffu, suA, 2);
        suB += __shfl_xor_sync(0xffffffffu, suB, 1);
        suB += __shfl_xor_sync(0xffffffffu, suB, 2);
        lA = lA * facA + suA;
        lB = lB * facB + suB;

        // ---- P fragments (fp16) ----
        u32 Aph[4][4];
#pragma unroll
        for (int kt = 0; kt < 4; kt++) {
            Aph[kt][0] = pack2h(s[2 * kt][0], s[2 * kt][1]);
            Aph[kt][1] = pack2h(s[2 * kt][2], s[2 * kt][3]);
            Aph[kt][2] = pack2h(s[2 * kt + 1][0], s[2 * kt + 1][1]);
            Aph[kt][3] = pack2h(s[2 * kt + 1][2], s[2 * kt + 1][3]);
        }

        // ---- O += P V (1-term), V^T in smem [d][j] ----
#pragma unroll
        for (int kt = 0; kt < 4; kt++) {
            u32 Bf[4][4];
            const u32 bkb = (u32)(kt * 32 + ((lane & 8) ? 16 : 0));
#pragma unroll
            for (int bt = 0; bt < 4; bt++) {
                u32 rb = vb + (u32)((bt * 16 + brow) * AROW) + bkb;
                ldsm_x4(rb, Bf[bt]);
            }
#pragma unroll
            for (int nt = 0; nt < 8; nt++)
                mma16816(o[nt], Aph[kt],
                         Bf[nt >> 1][(nt & 1) * 2], Bf[nt >> 1][(nt & 1) * 2 + 1]);
        }
    }

    // ---- epilogue: normalize, store fp16 ----
    float invA = 1.0f / lA, invB = 1.0f / lB;
    int rowA = b * NTOK + i0 + w * 16 + (lane >> 2);
#pragma unroll
    for (int nt = 0; nt < 8; nt++) {
        int col = h * DH + nt * 8 + 2 * (lane & 3);
        *(u32*)(oh + (size_t)rowA * DIMSZ + col) = pack2h(o[nt][0] * invA, o[nt][1] * invA);
        *(u32*)(oh + (size_t)(rowA + 8) * DIMSZ + col) = pack2h(o[nt][2] * invB, o[nt][3] * invB);
    }
}

// ---------------------------------------------------------------------------
extern "C" void kernel_launch(void* const* d_in, const int* in_sizes, int n_in,
                              void* d_out, int out_size) {
    const float* x    = (const float*)d_in[0];
    const float* rpb  = (const float*)d_in[1];
    const float* Wqkv = (const float*)d_in[2];
    const float* Wout = (const float*)d_in[3];
    const float* bout = (const float*)d_in[4];
    const float* lng  = (const float*)d_in[5];
    const float* lnb  = (const float*)d_in[6];
    float* out = (float*)d_out;

    u16 *xnh, *wqh, *woh, *qkh, *vth, *ath;
    cudaGetSymbolAddress((void**)&xnh, g_xnh);
    cudaGetSymbolAddress((void**)&wqh, g_wqh);
    cudaGetSymbolAddress((void**)&woh, g_woh);
    cudaGetSymbolAddress((void**)&qkh, g_qkvh);
    cudaGetSymbolAddress((void**)&vth, g_vth);
    cudaGetSymbolAddress((void**)&ath, g_atth);

    // 1) LN -> fp16
    ln_kernel<<<NROWS, 256>>>(x, lng, lnb, xnh);

    // 1b) weight prep (both weights, one launch)
    wprep_kernel<<<dim3(QKVN / 32, DIMSZ / 32, 2), 256>>>(Wqkv, Wout, wqh, woh);

    // 2) QKV projection (1-term, fp16 out, Q pre-scaled)
    cudaFuncSetAttribute(mma_gemm<1>, cudaFuncAttributeMaxDynamicSharedMemorySize, GEMM_SMEM);
    mma_gemm<1><<<dim3(QKVN / 128, NROWS / 128), 512, GEMM_SMEM>>>(
        xnh, wqh, nullptr, nullptr, qkh, QKVN);

    // 2b) V transpose
    vtrans_kernel<<<dim3(NTOK / 64, HEADS, BATCH), 256>>>(qkh, vth);

    // 3) attention (all 1-term fp16, bias prefetch)
    cudaFuncSetAttribute(attn_mma, cudaFuncAttributeMaxDynamicSharedMemorySize, ASMEM);
    attn_mma<<<dim3(NTOK / 128, HEADS, BATCH), 256, ASMEM>>>(
        qkh, vth, rpb, ath);

    // 4) output projection (1-term, fp32 out + bias)
    cudaFuncSetAttribute(mma_gemm<0>, cudaFuncAttributeMaxDynamicSharedMemorySize, GEMM_SMEM);
    mma_gemm<0><<<dim3(DIMSZ / 128, NROWS / 128), 512, GEMM_SMEM>>>(
        ath, woh, bout, out, nullptr, DIMSZ);
}